// round 11
// baseline (speedup 1.0000x reference)
#include <cuda_runtime.h>
#include <cuda_bf16.h>
#include <math.h>
#include <stdint.h>

#define BB 4
#define LL 2048
#define DD 768
#define DIc 1536
#define DSc 16
#define DRc 48
#define MROWS (BB*LL)      // 8192

// ---------------- scratch (static device globals; no allocation) ----------------
__device__ float g_ada[BB*3*DD];                 // shift|scale|gate per batch
__device__ __nv_bfloat16 g_xmh[MROWS*DD];        // modulated LN output (bf16)
__device__ float g_xz [MROWS*2*DIc];             // in_proj output (xi | z), fp32
__device__ float g_u  [MROWS*DIc];               // conv+silu output
__device__ float g_dbl[MROWS*80];                // x_proj output (dt|B|C)
__device__ float g_dl [MROWS*DIc];               // delta (softplus)
__device__ __nv_bfloat16 g_yzh[MROWS*DIc];       // (scan + u*D)*silu(z)  (bf16)
__device__ __nv_bfloat16 g_wih[2*DIc*DD];        // in_proj_w bf16
__device__ __nv_bfloat16 g_woh[DD*DIc];          // out_proj_w bf16

__device__ __forceinline__ float sigmoidf_(float x) {
    return 1.f / (1.f + __expf(-x));
}
__device__ __forceinline__ float ex2f(float x) {
    float y; asm("ex2.approx.ftz.f32 %0, %1;" : "=f"(y) : "f"(x)); return y;
}
__device__ __forceinline__ uint32_t smem_u32(const void* p) {
    uint32_t a;
    asm("{ .reg .u64 t; cvta.to.shared.u64 t, %1; cvt.u32.u64 %0, t; }"
        : "=r"(a) : "l"(p));
    return a;
}
__device__ __forceinline__ void ldsm_x4(uint32_t& r0, uint32_t& r1,
                                        uint32_t& r2, uint32_t& r3, uint32_t addr) {
    asm volatile("ldmatrix.sync.aligned.m8n8.x4.shared.b16 {%0,%1,%2,%3}, [%4];"
                 : "=r"(r0), "=r"(r1), "=r"(r2), "=r"(r3) : "r"(addr));
}
__device__ __forceinline__ void mma16816(float* d, uint32_t a0, uint32_t a1,
                                         uint32_t a2, uint32_t a3,
                                         uint32_t b0, uint32_t b1) {
    asm volatile("mma.sync.aligned.m16n8k16.row.col.f32.bf16.bf16.f32 "
                 "{%0,%1,%2,%3},{%4,%5,%6,%7},{%8,%9},{%0,%1,%2,%3};"
                 : "+f"(d[0]), "+f"(d[1]), "+f"(d[2]), "+f"(d[3])
                 : "r"(a0), "r"(a1), "r"(a2), "r"(a3), "r"(b0), "r"(b1));
}
#define CP16(dst, src) \
    asm volatile("cp.async.cg.shared.global [%0], [%1], 16;" :: "r"(dst), "l"(src))
#define CP_COMMIT() asm volatile("cp.async.commit_group;")
#define SW128(off) ((off) ^ (((off) >> 3) & 0x70))

// ---------------- K1: ada = silu(c) @ ada_w.T + ada_b  (warp per row) -------
__global__ void __launch_bounds__(256) ada_kernel(const float* __restrict__ c,
                                                  const float* __restrict__ ada_w,
                                                  const float* __restrict__ ada_b) {
    __shared__ float sc[2*DD];
    int b = blockIdx.y;
    for (int i = threadIdx.x; i < 2*DD; i += 256) {
        float v = c[b*2*DD + i];
        sc[i] = v * sigmoidf_(v);
    }
    __syncthreads();
    int w = threadIdx.x >> 5, lane = threadIdx.x & 31;
    int j = blockIdx.x * 8 + w;          // 0..2303
    const float4* w4 = (const float4*)(ada_w + (size_t)j * 2*DD);
    const float4* s4 = (const float4*)sc;
    float acc = 0.f;
    #pragma unroll 4
    for (int k = lane; k < (2*DD)/4; k += 32) {
        float4 wv = w4[k]; float4 s = s4[k];
        acc += wv.x*s.x + wv.y*s.y + wv.z*s.z + wv.w*s.w;
    }
    #pragma unroll
    for (int o = 16; o; o >>= 1)
        acc += __shfl_down_sync(0xffffffffu, acc, o);
    if (lane == 0) g_ada[b*3*DD + j] = acc + ada_b[j];
}

// ---------------- K2: LayerNorm + adaLN modulate -> bf16 ----------------
__global__ void ln_mod_kernel(const float* __restrict__ x,
                              const float* __restrict__ ln_w,
                              const float* __restrict__ ln_b) {
    int m = blockIdx.x;
    int b = m >> 11;
    const float* xr = x + (size_t)m * DD;
    float s = 0.f, ss = 0.f;
    for (int i = threadIdx.x; i < DD; i += 256) {
        float v = xr[i]; s += v; ss += v*v;
    }
    #pragma unroll
    for (int o = 16; o; o >>= 1) {
        s  += __shfl_down_sync(0xffffffffu, s, o);
        ss += __shfl_down_sync(0xffffffffu, ss, o);
    }
    __shared__ float rs[8], rss[8];
    __shared__ float smu, srstd;
    if ((threadIdx.x & 31) == 0) { rs[threadIdx.x>>5] = s; rss[threadIdx.x>>5] = ss; }
    __syncthreads();
    if (threadIdx.x == 0) {
        float ts = 0.f, tss = 0.f;
        #pragma unroll
        for (int i = 0; i < 8; ++i) { ts += rs[i]; tss += rss[i]; }
        float mu = ts * (1.f/DD);
        float var = tss * (1.f/DD) - mu*mu;
        smu = mu; srstd = rsqrtf(var + 1e-5f);
    }
    __syncthreads();
    float mu = smu, rstd = srstd;
    const float* ad = g_ada + b*3*DD;
    for (int i = threadIdx.x; i < DD; i += 256) {
        float v = (xr[i] - mu) * rstd * ln_w[i] + ln_b[i];
        v = v * (1.f + ad[DD + i]) + ad[i];
        g_xmh[(size_t)m*DD + i] = __float2bfloat16(v);
    }
}

// ---------------- weight fp32 -> bf16 conversion ----------------
__global__ void cvt_bf16_kernel(const float* __restrict__ in,
                                __nv_bfloat16* __restrict__ out, int n4) {
    int i = blockIdx.x * 256 + threadIdx.x;
    if (i >= n4) return;
    float4 v = ((const float4*)in)[i];
    __nv_bfloat16 o[4] = { __float2bfloat16(v.x), __float2bfloat16(v.y),
                           __float2bfloat16(v.z), __float2bfloat16(v.w) };
    ((uint2*)out)[i] = *(const uint2*)o;
}

// ---------------- bf16 mma.sync GEMM v2: C[m,n] = sum_k A[m,k]*B[n,k] -------
#define NSTG 3
#define TILEB 16384
template<int EPI>
__global__ void __launch_bounds__(256, 2) gemm_bf16(
    const __nv_bfloat16* __restrict__ A, const __nv_bfloat16* __restrict__ Bw,
    float* __restrict__ C, int N, int Kd,
    const float* __restrict__ xres, const float* __restrict__ ada)
{
    extern __shared__ __align__(128) char dynsm[];
    const int m0 = blockIdx.y * 128, n0 = blockIdx.x * 128;
    const int tid = threadIdx.x, wid = tid >> 5, lane = tid & 31;
    const int wm = wid >> 2, wn = wid & 3;

    const int lrow  = tid >> 1;
    const int lhalf = (tid & 1) * 64;
    uint32_t swo[4];
    #pragma unroll
    for (int j = 0; j < 4; ++j)
        swo[j] = SW128((uint32_t)(lrow*128 + lhalf + j*16));
    const char* Agp = (const char*)(A  + (size_t)(m0 + lrow) * Kd) + lhalf;
    const char* Bgp = (const char*)(Bw + (size_t)(n0 + lrow) * Kd) + lhalf;
    uint32_t sbase = smem_u32(dynsm);

    const int rowA = wm*64 + (lane & 15);
    const int colA = (lane >> 4) << 4;
    const int rowB = wn*32 + ((lane >> 4) << 3) + (lane & 7);
    const int colB = ((lane >> 3) & 1) << 4;

    float acc[4][4][4];
    #pragma unroll
    for (int i = 0; i < 4; ++i)
        #pragma unroll
        for (int j = 0; j < 4; ++j)
            #pragma unroll
            for (int q = 0; q < 4; ++q) acc[i][j][q] = 0.f;

    const int nt = Kd / 64;

    #pragma unroll
    for (int p = 0; p < 2; ++p) {
        uint32_t bA = sbase + p*2*TILEB;
        uint32_t bB = bA + TILEB;
        size_t kb = (size_t)p * 128;
        #pragma unroll
        for (int j = 0; j < 4; ++j) {
            CP16(bA + swo[j], Agp + kb + j*16);
            CP16(bB + swo[j], Bgp + kb + j*16);
        }
        CP_COMMIT();
    }

    for (int it = 0; it < nt; ++it) {
        if (it + 1 < nt) asm volatile("cp.async.wait_group 1;");
        else             asm volatile("cp.async.wait_group 0;");
        __syncthreads();
        if (it + 2 < nt) {
            int st = (it + 2) % NSTG;
            uint32_t bA = sbase + st*2*TILEB;
            uint32_t bB = bA + TILEB;
            size_t kb = (size_t)(it + 2) * 128;
            #pragma unroll
            for (int j = 0; j < 4; ++j) {
                CP16(bA + swo[j], Agp + kb + j*16);
                CP16(bB + swo[j], Bgp + kb + j*16);
            }
            CP_COMMIT();
        }
        int cs = it % NSTG;
        uint32_t bA = sbase + cs*2*TILEB;
        uint32_t bB = bA + TILEB;
        #pragma unroll
        for (int kf = 0; kf < 4; ++kf) {
            uint32_t af[4][4];
            #pragma unroll
            for (int mt = 0; mt < 4; ++mt) {
                uint32_t off = (uint32_t)((rowA + mt*16)*128 + kf*32 + colA);
                ldsm_x4(af[mt][0], af[mt][1], af[mt][2], af[mt][3], bA + SW128(off));
            }
            uint32_t bfv[2][4];
            #pragma unroll
            for (int np = 0; np < 2; ++np) {
                uint32_t off = (uint32_t)((rowB + np*16)*128 + kf*32 + colB);
                ldsm_x4(bfv[np][0], bfv[np][1], bfv[np][2], bfv[np][3], bB + SW128(off));
            }
            #pragma unroll
            for (int mt = 0; mt < 4; ++mt)
                #pragma unroll
                for (int nn = 0; nn < 4; ++nn) {
                    int np = nn >> 1, pr = nn & 1;
                    mma16816(acc[mt][nn], af[mt][0], af[mt][1], af[mt][2], af[mt][3],
                             bfv[np][pr*2], bfv[np][pr*2+1]);
                }
        }
    }

    #pragma unroll
    for (int mt = 0; mt < 4; ++mt) {
        #pragma unroll
        for (int nn = 0; nn < 4; ++nn) {
            int row = m0 + wm*64 + mt*16 + (lane >> 2);
            int col = n0 + wn*32 + nn*8 + (lane & 3)*2;
            float2 v0 = make_float2(acc[mt][nn][0], acc[mt][nn][1]);
            float2 v1 = make_float2(acc[mt][nn][2], acc[mt][nn][3]);
            if (EPI) {
                int bb = row >> 11;
                const float* gate = ada + bb*3*DD + 2*DD;
                float2 gv = *(const float2*)(gate + col);
                const float* xr0 = xres + (size_t)row * DD;
                float2 x0 = *(const float2*)(xr0 + col);
                float2 x1 = *(const float2*)(xr0 + 8*DD + col);
                v0.x = x0.x + gv.x*v0.x; v0.y = x0.y + gv.y*v0.y;
                v1.x = x1.x + gv.x*v1.x; v1.y = x1.y + gv.y*v1.y;
            }
            *(float2*)(C + (size_t)row * N + col)       = v0;
            *(float2*)(C + (size_t)(row + 8) * N + col) = v1;
        }
    }
}

// ---------------- K5: fused conv+silu + x_proj  (N=80, K=1536) --------------
// grid (5, 64): y = m-tile (128 rows), x = n-block (16 of 80 outputs).
// Per k-tile: stage xi (131 rows x 16 ch) from g_xz, conv+silu in smem -> uT,
// n-block 0 also writes u to g_u (needed by scan); then dot with x_proj_w.
__global__ void __launch_bounds__(256) xprojconv_kernel(const float* __restrict__ w,
                                                        const float* __restrict__ cw,
                                                        const float* __restrict__ cb) {
    __shared__ float xis[16][132];
    __shared__ float uT[16][128];
    __shared__ float ws[16][17];
    int m0 = blockIdx.y * 128;
    int n0 = blockIdx.x * 16;
    bool bnd = (m0 & (LL-1)) == 0;      // batch boundary: zero the 3 halo rows
    int tid = threadIdx.x;
    int nx = tid & 15, my = tid >> 4;
    float acc[8];
    #pragma unroll
    for (int i = 0; i < 8; ++i) acc[i] = 0.f;

    for (int k0 = 0; k0 < DIc; k0 += 16) {
        // stage xi rows m0-3 .. m0+127, 16 channels
        for (int idx = tid; idx < 131*4; idx += 256) {
            int r = idx >> 2, c4 = idx & 3;
            float4 v = make_float4(0.f, 0.f, 0.f, 0.f);
            if (!(bnd && r < 3)) {
                int gm = m0 - 3 + r;
                v = *(const float4*)(g_xz + (size_t)gm * (2*DIc) + k0 + c4*4);
            }
            xis[c4*4+0][r] = v.x; xis[c4*4+1][r] = v.y;
            xis[c4*4+2][r] = v.z; xis[c4*4+3][r] = v.w;
        }
        // stage x_proj weights: ws[k][n]
        {
            int r = tid >> 4, c = tid & 15;
            ws[c][r] = w[(size_t)(n0 + r)*DIc + k0 + c];
        }
        __syncthreads();
        // conv + silu -> uT[c][r]
        {
            int c = tid >> 4;
            int r0 = (tid & 15) * 8;
            const float* wc = cw + (size_t)(k0 + c) * 4;
            float w0 = wc[0], w1 = wc[1], w2 = wc[2], w3 = wc[3];
            float bv = cb[k0 + c];
            #pragma unroll
            for (int q = 0; q < 8; ++q) {
                int r = r0 + q;
                float a = bv + xis[c][r]*w0 + xis[c][r+1]*w1
                             + xis[c][r+2]*w2 + xis[c][r+3]*w3;
                uT[c][r] = a * sigmoidf_(a);
            }
        }
        __syncthreads();
        // n-block 0 persists u for the scan
        if (blockIdx.x == 0) {
            for (int idx = tid; idx < 512; idx += 256) {
                int r = idx >> 2, c4 = idx & 3;
                float4 v = make_float4(uT[c4*4+0][r], uT[c4*4+1][r],
                                       uT[c4*4+2][r], uT[c4*4+3][r]);
                *(float4*)(g_u + (size_t)(m0 + r)*DIc + k0 + c4*4) = v;
            }
        }
        // x_proj accumulate
        #pragma unroll
        for (int k = 0; k < 16; ++k) {
            float wv = ws[k][nx];
            float4 u0 = *(const float4*)&uT[k][my*8];
            float4 u1 = *(const float4*)&uT[k][my*8 + 4];
            acc[0] = fmaf(u0.x, wv, acc[0]); acc[1] = fmaf(u0.y, wv, acc[1]);
            acc[2] = fmaf(u0.z, wv, acc[2]); acc[3] = fmaf(u0.w, wv, acc[3]);
            acc[4] = fmaf(u1.x, wv, acc[4]); acc[5] = fmaf(u1.y, wv, acc[5]);
            acc[6] = fmaf(u1.z, wv, acc[6]); acc[7] = fmaf(u1.w, wv, acc[7]);
        }
        __syncthreads();
    }
    #pragma unroll
    for (int i = 0; i < 8; ++i)
        g_dbl[(size_t)(m0 + my*8 + i)*80 + n0 + nx] = acc[i];
}

// ---------------- K6: delta = softplus(dt @ dt_proj_w.T + b) ----------------
__global__ void __launch_bounds__(256) delta_kernel(const float* __restrict__ w,
                                                    const float* __restrict__ bias) {
    __shared__ float dt_sh[64][49];
    __shared__ float w_sh [64][49];
    int m0 = blockIdx.x * 64, j0 = blockIdx.y * 64;
    int tid = threadIdx.x;
    for (int f = tid; f < 64*48; f += 256) {
        int r = f / 48, cc = f - r*48;
        dt_sh[r][cc] = g_dbl[(size_t)(m0 + r)*80 + cc];
        w_sh [r][cc] = w[(size_t)(j0 + r)*48 + cc];
    }
    __syncthreads();
    int tx = tid & 15, ty = tid >> 4;
    float acc[4][4];
    #pragma unroll
    for (int i = 0; i < 4; ++i)
        #pragma unroll
        for (int j = 0; j < 4; ++j) acc[i][j] = 0.f;
    #pragma unroll 4
    for (int r = 0; r < 48; ++r) {
        float a[4], b_[4];
        #pragma unroll
        for (int i = 0; i < 4; ++i) a[i]  = dt_sh[ty*4 + i][r];
        #pragma unroll
        for (int j = 0; j < 4; ++j) b_[j] = w_sh[tx*4 + j][r];
        #pragma unroll
        for (int i = 0; i < 4; ++i)
            #pragma unroll
            for (int j = 0; j < 4; ++j)
                acc[i][j] = fmaf(a[i], b_[j], acc[i][j]);
    }
    #pragma unroll
    for (int i = 0; i < 4; ++i) {
        int m = m0 + ty*4 + i;
        #pragma unroll
        for (int j = 0; j < 4; ++j) {
            int jj = j0 + tx*4 + j;
            float t = acc[i][j] + bias[jj];
            float dl = (t > 15.f) ? t : log1pf(__expf(t));
            g_dl[(size_t)m*DIc + jj] = dl;
        }
    }
}

// ---------------- K7: selective scan, 4 lanes per channel (state-parallel) --
__global__ void __launch_bounds__(256) scan_kernel(const float* __restrict__ A_log,
                                                   const float* __restrict__ Dp) {
    int blk = blockIdx.x;               // 0..95; 24 blocks per batch
    int b   = blk / 24;
    int wid = threadIdx.x >> 5;
    int lane = threadIdx.x & 31;
    int sq  = lane & 3;                 // state quartet 0..3
    int di  = (blk % 24) * 64 + wid * 8 + (lane >> 2);
    float aa[4];
    #pragma unroll
    for (int j = 0; j < 4; ++j)
        aa[j] = -1.442695040888963f * __expf(A_log[di*16 + sq*4 + j]);
    float h[4] = {0.f, 0.f, 0.f, 0.f};
    float Dv = Dp[di];
    size_t mbase = (size_t)b * LL;

    size_t idx0 = mbase*DIc + di;
    float dl_c = g_dl[idx0];
    float uv_c = g_u[idx0];
    float zv_c = g_xz[mbase*(2*DIc) + DIc + di];
    float4 Bc = *(const float4*)(g_dbl + mbase*80 + 48 + sq*4);
    float4 Cc = *(const float4*)(g_dbl + mbase*80 + 64 + sq*4);

    for (int l = 0; l < LL; ++l) {
        float dl_n = 0.f, uv_n = 0.f, zv_n = 0.f;
        float4 Bn = make_float4(0.f,0.f,0.f,0.f), Cn = Bn;
        if (l + 1 < LL) {
            size_t mn = mbase + l + 1;
            size_t idn = mn*DIc + di;
            dl_n = g_dl[idn];
            uv_n = g_u[idn];
            zv_n = g_xz[mn*(2*DIc) + DIc + di];
            Bn = *(const float4*)(g_dbl + mn*80 + 48 + sq*4);
            Cn = *(const float4*)(g_dbl + mn*80 + 64 + sq*4);
        }
        float duv = dl_c * uv_c;
        float dA0 = ex2f(aa[0]*dl_c);
        float dA1 = ex2f(aa[1]*dl_c);
        float dA2 = ex2f(aa[2]*dl_c);
        float dA3 = ex2f(aa[3]*dl_c);
        h[0] = fmaf(dA0, h[0], duv*Bc.x);
        h[1] = fmaf(dA1, h[1], duv*Bc.y);
        h[2] = fmaf(dA2, h[2], duv*Bc.z);
        h[3] = fmaf(dA3, h[3], duv*Bc.w);
        float y = h[0]*Cc.x + h[1]*Cc.y + h[2]*Cc.z + h[3]*Cc.w;
        y += __shfl_xor_sync(0xffffffffu, y, 1);
        y += __shfl_xor_sync(0xffffffffu, y, 2);
        if (sq == 0) {
            float sz = zv_c * sigmoidf_(zv_c);
            g_yzh[(mbase + l)*DIc + di] = __float2bfloat16((y + uv_c*Dv) * sz);
        }
        dl_c = dl_n; uv_c = uv_n; zv_c = zv_n;
        Bc = Bn; Cc = Cn;
    }
}

// ---------------- launch ----------------
extern "C" void kernel_launch(void* const* d_in, const int* in_sizes, int n_in,
                              void* d_out, int out_size) {
    const float* x         = (const float*)d_in[0];
    const float* c         = (const float*)d_in[1];
    const float* ln_w      = (const float*)d_in[2];
    const float* ln_b      = (const float*)d_in[3];
    const float* ada_w     = (const float*)d_in[4];
    const float* ada_b     = (const float*)d_in[5];
    const float* in_proj_w = (const float*)d_in[6];
    const float* conv_w    = (const float*)d_in[7];
    const float* conv_b    = (const float*)d_in[8];
    const float* x_proj_w  = (const float*)d_in[9];
    const float* dt_proj_w = (const float*)d_in[10];
    const float* dt_proj_b = (const float*)d_in[11];
    const float* A_log     = (const float*)d_in[12];
    const float* D_param   = (const float*)d_in[13];
    const float* out_proj_w= (const float*)d_in[14];
    float* out = (float*)d_out;

    float *p_ada, *p_xz;
    __nv_bfloat16 *p_xmh, *p_yzh, *p_wih, *p_woh;
    cudaGetSymbolAddress((void**)&p_ada, g_ada);
    cudaGetSymbolAddress((void**)&p_xz,  g_xz);
    cudaGetSymbolAddress((void**)&p_xmh, g_xmh);
    cudaGetSymbolAddress((void**)&p_yzh, g_yzh);
    cudaGetSymbolAddress((void**)&p_wih, g_wih);
    cudaGetSymbolAddress((void**)&p_woh, g_woh);

    const int dynsmem = NSTG * 2 * TILEB;   // 96KB
    cudaFuncSetAttribute(gemm_bf16<0>, cudaFuncAttributeMaxDynamicSharedMemorySize, dynsmem);
    cudaFuncSetAttribute(gemm_bf16<1>, cudaFuncAttributeMaxDynamicSharedMemorySize, dynsmem);

    // Launch order: gemm_bf16<0> is index 3 (ncu profiles launch index 3).
    cvt_bf16_kernel<<<(2*DIc*DD/4 + 255)/256, 256>>>(in_proj_w, p_wih, 2*DIc*DD/4);  // 0
    ada_kernel<<<dim3(288, BB), 256>>>(c, ada_w, ada_b);                             // 1
    ln_mod_kernel<<<MROWS, 256>>>(x, ln_w, ln_b);                                    // 2
    gemm_bf16<0><<<dim3(3072/128, MROWS/128), 256, dynsmem>>>(                       // 3
        p_xmh, p_wih, p_xz, 2*DIc, DD, nullptr, nullptr);
    cvt_bf16_kernel<<<(DD*DIc/4 + 255)/256, 256>>>(out_proj_w, p_woh, DD*DIc/4);     // 4
    xprojconv_kernel<<<dim3(5, MROWS/128), 256>>>(x_proj_w, conv_w, conv_b);         // 5
    delta_kernel<<<dim3(MROWS/64, DIc/64), 256>>>(dt_proj_w, dt_proj_b);             // 6
    scan_kernel<<<96, 256>>>(A_log, D_param);                                        // 7
    gemm_bf16<1><<<dim3(DD/128, MROWS/128), 256, dynsmem>>>(                         // 8
        p_yzh, p_woh, out, DD, DIc, x, p_ada);
}

// round 13
// speedup vs baseline: 2.0544x; 2.0544x over previous
#include <cuda_runtime.h>
#include <cuda_bf16.h>
#include <math.h>
#include <stdint.h>

#define BB 4
#define LL 2048
#define DD 768
#define DIc 1536
#define DSc 16
#define DRc 48
#define MROWS (BB*LL)      // 8192
#define NCH 16             // scan chunks
#define LCH (LL/NCH)       // 128 steps per chunk

// ---------------- scratch (static device globals; no allocation) ----------------
__device__ float g_ada[BB*3*DD];                 // shift|scale|gate per batch
__device__ __nv_bfloat16 g_xmh[MROWS*DD];        // modulated LN output (bf16)
__device__ float g_xz [MROWS*2*DIc];             // in_proj output (xi | z), fp32
__device__ float g_u  [MROWS*DIc];               // conv+silu output
__device__ float g_dbl[MROWS*80];                // x_proj output (dt|B|C)
__device__ float g_dl [MROWS*DIc];               // delta (softplus)
__device__ __nv_bfloat16 g_yzh[MROWS*DIc];       // (scan + u*D)*silu(z)  (bf16)
__device__ __nv_bfloat16 g_wih[2*DIc*DD];        // in_proj_w bf16
__device__ __nv_bfloat16 g_woh[DD*DIc];          // out_proj_w bf16
__device__ float g_hq[BB*NCH*DIc*16];            // chunk partial end-state q
__device__ float g_hp[BB*NCH*DIc*16];            // chunk decay product P
__device__ float g_hs[BB*NCH*DIc*16];            // chunk true start-state H

__device__ __forceinline__ float sigmoidf_(float x) {
    return 1.f / (1.f + __expf(-x));
}
__device__ __forceinline__ float ex2f(float x) {
    float y; asm("ex2.approx.ftz.f32 %0, %1;" : "=f"(y) : "f"(x)); return y;
}
__device__ __forceinline__ uint32_t smem_u32(const void* p) {
    uint32_t a;
    asm("{ .reg .u64 t; cvta.to.shared.u64 t, %1; cvt.u32.u64 %0, t; }"
        : "=r"(a) : "l"(p));
    return a;
}
__device__ __forceinline__ void ldsm_x4(uint32_t& r0, uint32_t& r1,
                                        uint32_t& r2, uint32_t& r3, uint32_t addr) {
    asm volatile("ldmatrix.sync.aligned.m8n8.x4.shared.b16 {%0,%1,%2,%3}, [%4];"
                 : "=r"(r0), "=r"(r1), "=r"(r2), "=r"(r3) : "r"(addr));
}
__device__ __forceinline__ void mma16816(float* d, uint32_t a0, uint32_t a1,
                                         uint32_t a2, uint32_t a3,
                                         uint32_t b0, uint32_t b1) {
    asm volatile("mma.sync.aligned.m16n8k16.row.col.f32.bf16.bf16.f32 "
                 "{%0,%1,%2,%3},{%4,%5,%6,%7},{%8,%9},{%0,%1,%2,%3};"
                 : "+f"(d[0]), "+f"(d[1]), "+f"(d[2]), "+f"(d[3])
                 : "r"(a0), "r"(a1), "r"(a2), "r"(a3), "r"(b0), "r"(b1));
}
#define CP16(dst, src) \
    asm volatile("cp.async.cg.shared.global [%0], [%1], 16;" :: "r"(dst), "l"(src))
#define CP_COMMIT() asm volatile("cp.async.commit_group;")
#define SW128(off) ((off) ^ (((off) >> 3) & 0x70))

// ---------------- K1: ada = silu(c) @ ada_w.T + ada_b  (warp per row) -------
__global__ void __launch_bounds__(256) ada_kernel(const float* __restrict__ c,
                                                  const float* __restrict__ ada_w,
                                                  const float* __restrict__ ada_b) {
    __shared__ float sc[2*DD];
    int b = blockIdx.y;
    for (int i = threadIdx.x; i < 2*DD; i += 256) {
        float v = c[b*2*DD + i];
        sc[i] = v * sigmoidf_(v);
    }
    __syncthreads();
    int w = threadIdx.x >> 5, lane = threadIdx.x & 31;
    int j = blockIdx.x * 8 + w;
    const float4* w4 = (const float4*)(ada_w + (size_t)j * 2*DD);
    const float4* s4 = (const float4*)sc;
    float acc = 0.f;
    #pragma unroll 4
    for (int k = lane; k < (2*DD)/4; k += 32) {
        float4 wv = w4[k]; float4 s = s4[k];
        acc += wv.x*s.x + wv.y*s.y + wv.z*s.z + wv.w*s.w;
    }
    #pragma unroll
    for (int o = 16; o; o >>= 1)
        acc += __shfl_down_sync(0xffffffffu, acc, o);
    if (lane == 0) g_ada[b*3*DD + j] = acc + ada_b[j];
}

// ---------------- K2: LayerNorm + adaLN modulate -> bf16 ----------------
__global__ void ln_mod_kernel(const float* __restrict__ x,
                              const float* __restrict__ ln_w,
                              const float* __restrict__ ln_b) {
    int m = blockIdx.x;
    int b = m >> 11;
    const float* xr = x + (size_t)m * DD;
    float s = 0.f, ss = 0.f;
    for (int i = threadIdx.x; i < DD; i += 256) {
        float v = xr[i]; s += v; ss += v*v;
    }
    #pragma unroll
    for (int o = 16; o; o >>= 1) {
        s  += __shfl_down_sync(0xffffffffu, s, o);
        ss += __shfl_down_sync(0xffffffffu, ss, o);
    }
    __shared__ float rs[8], rss[8];
    __shared__ float smu, srstd;
    if ((threadIdx.x & 31) == 0) { rs[threadIdx.x>>5] = s; rss[threadIdx.x>>5] = ss; }
    __syncthreads();
    if (threadIdx.x == 0) {
        float ts = 0.f, tss = 0.f;
        #pragma unroll
        for (int i = 0; i < 8; ++i) { ts += rs[i]; tss += rss[i]; }
        float mu = ts * (1.f/DD);
        float var = tss * (1.f/DD) - mu*mu;
        smu = mu; srstd = rsqrtf(var + 1e-5f);
    }
    __syncthreads();
    float mu = smu, rstd = srstd;
    const float* ad = g_ada + b*3*DD;
    for (int i = threadIdx.x; i < DD; i += 256) {
        float v = (xr[i] - mu) * rstd * ln_w[i] + ln_b[i];
        v = v * (1.f + ad[DD + i]) + ad[i];
        g_xmh[(size_t)m*DD + i] = __float2bfloat16(v);
    }
}

// ---------------- weight fp32 -> bf16 conversion ----------------
__global__ void cvt_bf16_kernel(const float* __restrict__ in,
                                __nv_bfloat16* __restrict__ out, int n4) {
    int i = blockIdx.x * 256 + threadIdx.x;
    if (i >= n4) return;
    float4 v = ((const float4*)in)[i];
    __nv_bfloat16 o[4] = { __float2bfloat16(v.x), __float2bfloat16(v.y),
                           __float2bfloat16(v.z), __float2bfloat16(v.w) };
    ((uint2*)out)[i] = *(const uint2*)o;
}

// ---------------- bf16 mma.sync GEMM v2 ----------------
#define NSTG 3
#define TILEB 16384
template<int EPI>
__global__ void __launch_bounds__(256, 2) gemm_bf16(
    const __nv_bfloat16* __restrict__ A, const __nv_bfloat16* __restrict__ Bw,
    float* __restrict__ C, int N, int Kd,
    const float* __restrict__ xres, const float* __restrict__ ada)
{
    extern __shared__ __align__(128) char dynsm[];
    const int m0 = blockIdx.y * 128, n0 = blockIdx.x * 128;
    const int tid = threadIdx.x, wid = tid >> 5, lane = tid & 31;
    const int wm = wid >> 2, wn = wid & 3;

    const int lrow  = tid >> 1;
    const int lhalf = (tid & 1) * 64;
    uint32_t swo[4];
    #pragma unroll
    for (int j = 0; j < 4; ++j)
        swo[j] = SW128((uint32_t)(lrow*128 + lhalf + j*16));
    const char* Agp = (const char*)(A  + (size_t)(m0 + lrow) * Kd) + lhalf;
    const char* Bgp = (const char*)(Bw + (size_t)(n0 + lrow) * Kd) + lhalf;
    uint32_t sbase = smem_u32(dynsm);

    const int rowA = wm*64 + (lane & 15);
    const int colA = (lane >> 4) << 4;
    const int rowB = wn*32 + ((lane >> 4) << 3) + (lane & 7);
    const int colB = ((lane >> 3) & 1) << 4;

    float acc[4][4][4];
    #pragma unroll
    for (int i = 0; i < 4; ++i)
        #pragma unroll
        for (int j = 0; j < 4; ++j)
            #pragma unroll
            for (int q = 0; q < 4; ++q) acc[i][j][q] = 0.f;

    const int nt = Kd / 64;

    #pragma unroll
    for (int p = 0; p < 2; ++p) {
        uint32_t bA = sbase + p*2*TILEB;
        uint32_t bB = bA + TILEB;
        size_t kb = (size_t)p * 128;
        #pragma unroll
        for (int j = 0; j < 4; ++j) {
            CP16(bA + swo[j], Agp + kb + j*16);
            CP16(bB + swo[j], Bgp + kb + j*16);
        }
        CP_COMMIT();
    }

    for (int it = 0; it < nt; ++it) {
        if (it + 1 < nt) asm volatile("cp.async.wait_group 1;");
        else             asm volatile("cp.async.wait_group 0;");
        __syncthreads();
        if (it + 2 < nt) {
            int st = (it + 2) % NSTG;
            uint32_t bA = sbase + st*2*TILEB;
            uint32_t bB = bA + TILEB;
            size_t kb = (size_t)(it + 2) * 128;
            #pragma unroll
            for (int j = 0; j < 4; ++j) {
                CP16(bA + swo[j], Agp + kb + j*16);
                CP16(bB + swo[j], Bgp + kb + j*16);
            }
            CP_COMMIT();
        }
        int cs = it % NSTG;
        uint32_t bA = sbase + cs*2*TILEB;
        uint32_t bB = bA + TILEB;
        #pragma unroll
        for (int kf = 0; kf < 4; ++kf) {
            uint32_t af[4][4];
            #pragma unroll
            for (int mt = 0; mt < 4; ++mt) {
                uint32_t off = (uint32_t)((rowA + mt*16)*128 + kf*32 + colA);
                ldsm_x4(af[mt][0], af[mt][1], af[mt][2], af[mt][3], bA + SW128(off));
            }
            uint32_t bfv[2][4];
            #pragma unroll
            for (int np = 0; np < 2; ++np) {
                uint32_t off = (uint32_t)((rowB + np*16)*128 + kf*32 + colB);
                ldsm_x4(bfv[np][0], bfv[np][1], bfv[np][2], bfv[np][3], bB + SW128(off));
            }
            #pragma unroll
            for (int mt = 0; mt < 4; ++mt)
                #pragma unroll
                for (int nn = 0; nn < 4; ++nn) {
                    int np = nn >> 1, pr = nn & 1;
                    mma16816(acc[mt][nn], af[mt][0], af[mt][1], af[mt][2], af[mt][3],
                             bfv[np][pr*2], bfv[np][pr*2+1]);
                }
        }
    }

    #pragma unroll
    for (int mt = 0; mt < 4; ++mt) {
        #pragma unroll
        for (int nn = 0; nn < 4; ++nn) {
            int row = m0 + wm*64 + mt*16 + (lane >> 2);
            int col = n0 + wn*32 + nn*8 + (lane & 3)*2;
            float2 v0 = make_float2(acc[mt][nn][0], acc[mt][nn][1]);
            float2 v1 = make_float2(acc[mt][nn][2], acc[mt][nn][3]);
            if (EPI) {
                int bb = row >> 11;
                const float* gate = ada + bb*3*DD + 2*DD;
                float2 gv = *(const float2*)(gate + col);
                const float* xr0 = xres + (size_t)row * DD;
                float2 x0 = *(const float2*)(xr0 + col);
                float2 x1 = *(const float2*)(xr0 + 8*DD + col);
                v0.x = x0.x + gv.x*v0.x; v0.y = x0.y + gv.y*v0.y;
                v1.x = x1.x + gv.x*v1.x; v1.y = x1.y + gv.y*v1.y;
            }
            *(float2*)(C + (size_t)row * N + col)       = v0;
            *(float2*)(C + (size_t)(row + 8) * N + col) = v1;
        }
    }
}

// ---------------- K4: causal depthwise conv (K=4) + bias + silu ----------------
__global__ void conv_silu_kernel(const float* __restrict__ cw,
                                 const float* __restrict__ cb) {
    int id = blockIdx.x * 256 + threadIdx.x;
    if (id >= MROWS*DIc) return;
    int ch = id % DIc;
    int m  = id / DIc;
    int l  = m & (LL - 1);
    float acc = cb[ch];
    const float* w = cw + ch*4;
    #pragma unroll
    for (int k = 0; k < 4; ++k) {
        int llv = l - 3 + k;
        if (llv >= 0)
            acc += g_xz[(size_t)(m - 3 + k) * (2*DIc) + ch] * w[k];
    }
    g_u[id] = acc * sigmoidf_(acc);
}

// ---------------- K5: dbl = u @ x_proj_w.T  (N=80, K=1536) ----------------
__global__ void __launch_bounds__(256) xproj_kernel(const float* __restrict__ w) {
    __shared__ float uT[16][128];
    __shared__ float ws[16][17];
    int m0 = blockIdx.x * 128;
    int n0 = blockIdx.y * 16;
    int tid = threadIdx.x;
    int nx = tid & 15, my = tid >> 4;
    float acc[8];
    #pragma unroll
    for (int i = 0; i < 8; ++i) acc[i] = 0.f;
    for (int k0 = 0; k0 < DIc; k0 += 16) {
        #pragma unroll
        for (int q = 0; q < 2; ++q) {
            int ff = tid + q*256;
            int r  = ff >> 2;
            int c4 = (ff & 3) * 4;
            float4 v = *(const float4*)(g_u + (size_t)(m0 + r)*DIc + k0 + c4);
            uT[c4+0][r] = v.x; uT[c4+1][r] = v.y; uT[c4+2][r] = v.z; uT[c4+3][r] = v.w;
        }
        {
            int r = tid >> 4, c = tid & 15;
            ws[c][r] = w[(size_t)(n0 + r)*DIc + k0 + c];
        }
        __syncthreads();
        #pragma unroll
        for (int k = 0; k < 16; ++k) {
            float wv = ws[k][nx];
            float4 u0 = *(const float4*)&uT[k][my*8];
            float4 u1 = *(const float4*)&uT[k][my*8 + 4];
            acc[0] = fmaf(u0.x, wv, acc[0]); acc[1] = fmaf(u0.y, wv, acc[1]);
            acc[2] = fmaf(u0.z, wv, acc[2]); acc[3] = fmaf(u0.w, wv, acc[3]);
            acc[4] = fmaf(u1.x, wv, acc[4]); acc[5] = fmaf(u1.y, wv, acc[5]);
            acc[6] = fmaf(u1.z, wv, acc[6]); acc[7] = fmaf(u1.w, wv, acc[7]);
        }
        __syncthreads();
    }
    #pragma unroll
    for (int i = 0; i < 8; ++i)
        g_dbl[(size_t)(m0 + my*8 + i)*80 + n0 + nx] = acc[i];
}

// ---------------- K6: delta = softplus(dt @ dt_proj_w.T + b) ----------------
__global__ void __launch_bounds__(256) delta_kernel(const float* __restrict__ w,
                                                    const float* __restrict__ bias) {
    __shared__ float dt_sh[64][49];
    __shared__ float w_sh [64][49];
    int m0 = blockIdx.x * 64, j0 = blockIdx.y * 64;
    int tid = threadIdx.x;
    for (int f = tid; f < 64*48; f += 256) {
        int r = f / 48, cc = f - r*48;
        dt_sh[r][cc] = g_dbl[(size_t)(m0 + r)*80 + cc];
        w_sh [r][cc] = w[(size_t)(j0 + r)*48 + cc];
    }
    __syncthreads();
    int tx = tid & 15, ty = tid >> 4;
    float acc[4][4];
    #pragma unroll
    for (int i = 0; i < 4; ++i)
        #pragma unroll
        for (int j = 0; j < 4; ++j) acc[i][j] = 0.f;
    #pragma unroll 4
    for (int r = 0; r < 48; ++r) {
        float a[4], b_[4];
        #pragma unroll
        for (int i = 0; i < 4; ++i) a[i]  = dt_sh[ty*4 + i][r];
        #pragma unroll
        for (int j = 0; j < 4; ++j) b_[j] = w_sh[tx*4 + j][r];
        #pragma unroll
        for (int i = 0; i < 4; ++i)
            #pragma unroll
            for (int j = 0; j < 4; ++j)
                acc[i][j] = fmaf(a[i], b_[j], acc[i][j]);
    }
    #pragma unroll
    for (int i = 0; i < 4; ++i) {
        int m = m0 + ty*4 + i;
        #pragma unroll
        for (int j = 0; j < 4; ++j) {
            int jj = j0 + tx*4 + j;
            float t = acc[i][j] + bias[jj];
            float dl = (t > 15.f) ? t : log1pf(__expf(t));
            g_dl[(size_t)m*DIc + jj] = dl;
        }
    }
}

// ---------------- K7a: scan phase A — per-chunk partials (h from 0, P=prod dA)
__global__ void __launch_bounds__(256) scanA_kernel(const float* __restrict__ A_log) {
    int blk = blockIdx.x;               // 0..95
    int ch  = blockIdx.y;               // chunk 0..15
    int b   = blk / 24;
    int wid = threadIdx.x >> 5;
    int lane = threadIdx.x & 31;
    int sq  = lane & 3;
    int di  = (blk % 24) * 64 + wid * 8 + (lane >> 2);
    float aa[4];
    #pragma unroll
    for (int j = 0; j < 4; ++j)
        aa[j] = -1.442695040888963f * __expf(A_log[di*16 + sq*4 + j]);
    float h[4] = {0.f,0.f,0.f,0.f};
    float P[4] = {1.f,1.f,1.f,1.f};
    size_t mbase = (size_t)b * LL + (size_t)ch * LCH;

    size_t idx0 = mbase*DIc + di;
    float dl_c = g_dl[idx0];
    float uv_c = g_u[idx0];
    float4 Bc = *(const float4*)(g_dbl + mbase*80 + 48 + sq*4);

    for (int l = 0; l < LCH; ++l) {
        float dl_n = 0.f, uv_n = 0.f;
        float4 Bn = make_float4(0.f,0.f,0.f,0.f);
        if (l + 1 < LCH) {
            size_t mn = mbase + l + 1;
            size_t idn = mn*DIc + di;
            dl_n = g_dl[idn];
            uv_n = g_u[idn];
            Bn = *(const float4*)(g_dbl + mn*80 + 48 + sq*4);
        }
        float duv = dl_c * uv_c;
        float dA0 = ex2f(aa[0]*dl_c);
        float dA1 = ex2f(aa[1]*dl_c);
        float dA2 = ex2f(aa[2]*dl_c);
        float dA3 = ex2f(aa[3]*dl_c);
        h[0] = fmaf(dA0, h[0], duv*Bc.x);  P[0] *= dA0;
        h[1] = fmaf(dA1, h[1], duv*Bc.y);  P[1] *= dA1;
        h[2] = fmaf(dA2, h[2], duv*Bc.z);  P[2] *= dA2;
        h[3] = fmaf(dA3, h[3], duv*Bc.w);  P[3] *= dA3;
        dl_c = dl_n; uv_c = uv_n; Bc = Bn;
    }
    size_t o = (((size_t)(b*NCH + ch) * DIc) + di) * 16 + sq*4;
    *(float4*)(g_hq + o) = make_float4(h[0], h[1], h[2], h[3]);
    *(float4*)(g_hp + o) = make_float4(P[0], P[1], P[2], P[3]);
}

// ---------------- K7b: scan phase B — sequential chunk fix-up ----------------
__global__ void __launch_bounds__(256) scanB_kernel() {
    int idx = blockIdx.x * 256 + threadIdx.x;      // 0 .. BB*DIc*16-1
    int s  = idx & 15;
    int di = (idx >> 4) % DIc;
    int b  = idx / (DIc * 16);
    float H = 0.f;
    #pragma unroll
    for (int c = 0; c < NCH; ++c) {
        size_t o = (((size_t)(b*NCH + c) * DIc) + di) * 16 + s;
        g_hs[o] = H;
        H = g_hp[o] * H + g_hq[o];
    }
}

// ---------------- K7c: scan phase C — re-run with true start, emit output ----
__global__ void __launch_bounds__(256) scanC_kernel(const float* __restrict__ A_log,
                                                    const float* __restrict__ Dp) {
    int blk = blockIdx.x;               // 0..95
    int ch  = blockIdx.y;               // chunk 0..15
    int b   = blk / 24;
    int wid = threadIdx.x >> 5;
    int lane = threadIdx.x & 31;
    int sq  = lane & 3;
    int di  = (blk % 24) * 64 + wid * 8 + (lane >> 2);
    float aa[4];
    #pragma unroll
    for (int j = 0; j < 4; ++j)
        aa[j] = -1.442695040888963f * __expf(A_log[di*16 + sq*4 + j]);
    float h[4];
    {
        size_t o = (((size_t)(b*NCH + ch) * DIc) + di) * 16 + sq*4;
        float4 hv = *(const float4*)(g_hs + o);
        h[0] = hv.x; h[1] = hv.y; h[2] = hv.z; h[3] = hv.w;
    }
    float Dv = Dp[di];
    size_t mbase = (size_t)b * LL + (size_t)ch * LCH;

    size_t idx0 = mbase*DIc + di;
    float dl_c = g_dl[idx0];
    float uv_c = g_u[idx0];
    float zv_c = g_xz[mbase*(2*DIc) + DIc + di];
    float4 Bc = *(const float4*)(g_dbl + mbase*80 + 48 + sq*4);
    float4 Cc = *(const float4*)(g_dbl + mbase*80 + 64 + sq*4);

    for (int l = 0; l < LCH; ++l) {
        float dl_n = 0.f, uv_n = 0.f, zv_n = 0.f;
        float4 Bn = make_float4(0.f,0.f,0.f,0.f), Cn = Bn;
        if (l + 1 < LCH) {
            size_t mn = mbase + l + 1;
            size_t idn = mn*DIc + di;
            dl_n = g_dl[idn];
            uv_n = g_u[idn];
            zv_n = g_xz[mn*(2*DIc) + DIc + di];
            Bn = *(const float4*)(g_dbl + mn*80 + 48 + sq*4);
            Cn = *(const float4*)(g_dbl + mn*80 + 64 + sq*4);
        }
        float duv = dl_c * uv_c;
        float dA0 = ex2f(aa[0]*dl_c);
        float dA1 = ex2f(aa[1]*dl_c);
        float dA2 = ex2f(aa[2]*dl_c);
        float dA3 = ex2f(aa[3]*dl_c);
        h[0] = fmaf(dA0, h[0], duv*Bc.x);
        h[1] = fmaf(dA1, h[1], duv*Bc.y);
        h[2] = fmaf(dA2, h[2], duv*Bc.z);
        h[3] = fmaf(dA3, h[3], duv*Bc.w);
        float y = h[0]*Cc.x + h[1]*Cc.y + h[2]*Cc.z + h[3]*Cc.w;
        y += __shfl_xor_sync(0xffffffffu, y, 1);
        y += __shfl_xor_sync(0xffffffffu, y, 2);
        if (sq == 0) {
            float sz = zv_c * sigmoidf_(zv_c);
            g_yzh[(mbase + l)*DIc + di] = __float2bfloat16((y + uv_c*Dv) * sz);
        }
        dl_c = dl_n; uv_c = uv_n; zv_c = zv_n;
        Bc = Bn; Cc = Cn;
    }
}

// ---------------- launch ----------------
extern "C" void kernel_launch(void* const* d_in, const int* in_sizes, int n_in,
                              void* d_out, int out_size) {
    const float* x         = (const float*)d_in[0];
    const float* c         = (const float*)d_in[1];
    const float* ln_w      = (const float*)d_in[2];
    const float* ln_b      = (const float*)d_in[3];
    const float* ada_w     = (const float*)d_in[4];
    const float* ada_b     = (const float*)d_in[5];
    const float* in_proj_w = (const float*)d_in[6];
    const float* conv_w    = (const float*)d_in[7];
    const float* conv_b    = (const float*)d_in[8];
    const float* x_proj_w  = (const float*)d_in[9];
    const float* dt_proj_w = (const float*)d_in[10];
    const float* dt_proj_b = (const float*)d_in[11];
    const float* A_log     = (const float*)d_in[12];
    const float* D_param   = (const float*)d_in[13];
    const float* out_proj_w= (const float*)d_in[14];
    float* out = (float*)d_out;

    float *p_ada, *p_xz;
    __nv_bfloat16 *p_xmh, *p_yzh, *p_wih, *p_woh;
    cudaGetSymbolAddress((void**)&p_ada, g_ada);
    cudaGetSymbolAddress((void**)&p_xz,  g_xz);
    cudaGetSymbolAddress((void**)&p_xmh, g_xmh);
    cudaGetSymbolAddress((void**)&p_yzh, g_yzh);
    cudaGetSymbolAddress((void**)&p_wih, g_wih);
    cudaGetSymbolAddress((void**)&p_woh, g_woh);

    const int dynsmem = NSTG * 2 * TILEB;   // 96KB
    cudaFuncSetAttribute(gemm_bf16<0>, cudaFuncAttributeMaxDynamicSharedMemorySize, dynsmem);
    cudaFuncSetAttribute(gemm_bf16<1>, cudaFuncAttributeMaxDynamicSharedMemorySize, dynsmem);

    cvt_bf16_kernel<<<(2*DIc*DD/4 + 255)/256, 256>>>(in_proj_w, p_wih, 2*DIc*DD/4);  // 0
    ada_kernel<<<dim3(288, BB), 256>>>(c, ada_w, ada_b);                             // 1
    ln_mod_kernel<<<MROWS, 256>>>(x, ln_w, ln_b);                                    // 2
    gemm_bf16<0><<<dim3(3072/128, MROWS/128), 256, dynsmem>>>(                       // 3
        p_xmh, p_wih, p_xz, 2*DIc, DD, nullptr, nullptr);
    cvt_bf16_kernel<<<(DD*DIc/4 + 255)/256, 256>>>(out_proj_w, p_woh, DD*DIc/4);     // 4
    conv_silu_kernel<<<(MROWS*DIc)/256, 256>>>(conv_w, conv_b);                      // 5
    xproj_kernel<<<dim3(MROWS/128, 5), 256>>>(x_proj_w);                             // 6
    delta_kernel<<<dim3(MROWS/64, DIc/64), 256>>>(dt_proj_w, dt_proj_b);             // 7
    scanA_kernel<<<dim3(96, NCH), 256>>>(A_log);                                     // 8
    scanB_kernel<<<(BB*DIc*16)/256, 256>>>();                                        // 9
    scanC_kernel<<<dim3(96, NCH), 256>>>(A_log, D_param);                            // 10
    gemm_bf16<1><<<dim3(DD/128, MROWS/128), 256, dynsmem>>>(                         // 11
        p_yzh, p_woh, out, DD, DIc, x, p_ada);
}